// round 14
// baseline (speedup 1.0000x reference)
#include <cuda_runtime.h>
#include <cuda_fp16.h>
#include <cstdint>

#define N_ROWS 65536
#define DIM    256
#define NCODES 1024
#define BM     256
#define NTHREADS 512
#define EPSF   6.0e-3f
#define CAND_MAX 32

__device__ float    g_cnorm[NCODES];
__device__ float    g_znorm[N_ROWS];
__device__ int      g_codes[N_ROWS];
__device__ double   g_loss_acc;
__device__ unsigned g_done;
__device__ __half   g_cbh[NCODES * DIM];

// ---- smem layout (bytes) ----
#define O_ZS   0                 // [256] rows x 264-half pitch = 135168
#define O_CBS  135168            // 2 x [128][72] half = 36864
#define O_CN   172032            // [1024] float = 4096
#define O_RMIN 176128            // [256] uint = 1024
#define O_CNT  177152            // [256] int = 1024
#define O_CAND 178176            // [256][32] u16 = 16384
#define O_BEST 194560            // [256] u64 = 2048
#define SMEM_SZ 196608

__device__ __forceinline__ uint32_t smaddr(const void* p) {
    return (uint32_t)__cvta_generic_to_shared(p);
}
#define LDSM_X4(r0,r1,r2,r3,a) \
    asm volatile("ldmatrix.sync.aligned.m8n8.x4.shared.b16 {%0,%1,%2,%3}, [%4];" \
        : "=r"(r0),"=r"(r1),"=r"(r2),"=r"(r3) : "r"(a))
// fp16-accumulator HMMA: D(f16x2 x2) = A*B + C ; half the acc registers,
// potentially 2x the per-instruction rate on the legacy (non-tcgen05) path.
#define MMA16816H(d,a,b0,b1) \
    asm volatile("mma.sync.aligned.m16n8k16.row.col.f16.f16.f16.f16 " \
        "{%0,%1},{%2,%3,%4,%5},{%6,%7},{%0,%1};" \
        : "+r"((d)[0]),"+r"((d)[1]) \
        : "r"((a)[0]),"r"((a)[1]),"r"((a)[2]),"r"((a)[3]),"r"(b0),"r"(b1))

// monotone encode for floats in (-1,1): s+1 > 0
__device__ __forceinline__ uint32_t enc_s(float s) { return __float_as_uint(s + 1.0f); }
__device__ __forceinline__ float dec_s(uint32_t u) { return __uint_as_float(u) - 1.0f; }

// exact reference-rounding distance: d = fl(fl(zn+cn) - fl(2*dot)),
// dot = sequential ascending-d fp32 FMA chain.
__device__ __forceinline__ float exact_d(const float* __restrict__ z,
                                         const float* __restrict__ cb,
                                         int rg, int c, float zn, float cn) {
    const float4* zp = reinterpret_cast<const float4*>(z + (size_t)rg * DIM);
    const float4* cp = reinterpret_cast<const float4*>(cb + (size_t)c * DIM);
    float dot = 0.0f;
    #pragma unroll 8
    for (int t = 0; t < DIM / 4; t++) {
        float4 zv = __ldg(zp + t);
        float4 cv = __ldg(cp + t);
        dot = __fmaf_rn(zv.x, cv.x, dot);
        dot = __fmaf_rn(zv.y, cv.y, dot);
        dot = __fmaf_rn(zv.z, cv.z, dot);
        dot = __fmaf_rn(zv.w, cv.w, dot);
    }
    return __fsub_rn(__fadd_rn(zn, cn), __fmul_rn(2.0f, dot));
}

// -------------------------------------------------------------------------
// Prep: codebook norms + codebook fp16 (strict in-order rounding) + zero accs.
// -------------------------------------------------------------------------
__global__ void prep_kernel(const float* __restrict__ cb) {
    int i = blockIdx.x * blockDim.x + threadIdx.x;   // 0..1023
    if (i == 0) { g_loss_acc = 0.0; g_done = 0u; }
    const float4* row = reinterpret_cast<const float4*>(cb + (size_t)i * DIM);
    __half2* dst = reinterpret_cast<__half2*>(g_cbh + (size_t)i * DIM);
    float s = 0.0f;
    #pragma unroll
    for (int t = 0; t < DIM / 4; t++) {
        float4 v = row[t];
        s = __fadd_rn(s, __fmul_rn(v.x, v.x));
        s = __fadd_rn(s, __fmul_rn(v.y, v.y));
        s = __fadd_rn(s, __fmul_rn(v.z, v.z));
        s = __fadd_rn(s, __fmul_rn(v.w, v.w));
        dst[2 * t]     = __floats2half2_rn(v.x, v.y);
        dst[2 * t + 1] = __floats2half2_rn(v.z, v.w);
    }
    g_cnorm[i] = s;
}

// -------------------------------------------------------------------------
// Coalesced z row norms: stage 32 rows via smem, then 32 in-order chains.
// -------------------------------------------------------------------------
#define ZROWS 32
__global__ void znorm_kernel(const float* __restrict__ z) {
    __shared__ float buf[ZROWS][DIM + 1];   // pitch 257 -> conflict-free
    const int tid = threadIdx.x;
    const int r0  = blockIdx.x * ZROWS;

    #pragma unroll
    for (int k = 0; k < (ZROWS * DIM / 4) / 256; k++) {
        int i = tid + k * 256;
        int row = i >> 6, c4 = i & 63;
        float4 v = __ldg(reinterpret_cast<const float4*>(
            z + (size_t)(r0 + row) * DIM) + c4);
        buf[row][c4 * 4 + 0] = v.x;
        buf[row][c4 * 4 + 1] = v.y;
        buf[row][c4 * 4 + 2] = v.z;
        buf[row][c4 * 4 + 3] = v.w;
    }
    __syncthreads();

    if (tid < ZROWS) {
        float s = 0.0f;
        #pragma unroll 8
        for (int i = 0; i < DIM; i++)
            s = __fadd_rn(s, __fmul_rn(buf[tid][i], buf[tid][i]));
        g_znorm[r0 + tid] = s;
    }
}

// -------------------------------------------------------------------------
// Screen: fp16 mma WITH fp16 accumulators (warp tile 32x64, 16 warps/CTA)
// + fused running-min candidate collection + exact fp32-chain refine.
// -------------------------------------------------------------------------
__global__ __launch_bounds__(NTHREADS, 1)
void screen_kernel(const float* __restrict__ z, const float* __restrict__ cb) {
    extern __shared__ unsigned char sm[];
    __half* z_s  = reinterpret_cast<__half*>(sm + O_ZS);
    __half* cb_s = reinterpret_cast<__half*>(sm + O_CBS);
    float*  cn_s = reinterpret_cast<float*>(sm + O_CN);
    uint32_t* rmin_s = reinterpret_cast<uint32_t*>(sm + O_RMIN);
    int* cnt_s = reinterpret_cast<int*>(sm + O_CNT);
    unsigned short* cand_s = reinterpret_cast<unsigned short*>(sm + O_CAND);
    unsigned long long* best_s = reinterpret_cast<unsigned long long*>(sm + O_BEST);

    const int tid  = threadIdx.x;
    const int lane = tid & 31;
    const int wid  = tid >> 5;
    const int warp_m = wid & 7;   // rows warp_m*32..+31
    const int warp_n = wid >> 3;  // codes warp_n*64..+63
    const int r0g = blockIdx.x * BM;

    // ---- init + load z tile (fp32 -> fp16 convert) + cn ----
    {
        const int zrow = tid >> 1, zh = tid & 1;
        const float4* zsrc = reinterpret_cast<const float4*>(
            z + (size_t)(r0g + zrow) * DIM + zh * 128);
        __half2* zdst = reinterpret_cast<__half2*>(z_s + zrow * 264 + zh * 128);
        #pragma unroll 8
        for (int t = 0; t < 32; t++) {
            float4 v = zsrc[t];
            zdst[2 * t]     = __floats2half2_rn(v.x, v.y);
            zdst[2 * t + 1] = __floats2half2_rn(v.z, v.w);
        }
        if (tid < 256)
            reinterpret_cast<float4*>(cn_s)[tid] =
                reinterpret_cast<const float4*>(g_cnorm)[tid];
        if (tid < BM) {
            rmin_s[tid] = __float_as_uint(100.0f);
            cnt_s[tid] = 0;
            best_s[tid] = 0xFFFFFFFFFFFFFFFFull;
        }
    }

    // B chunk loader mapping (128 codes x 64 dims fp16 per chunk, 16KB)
    const int ldn = tid >> 2, ldq = tid & 3;   // 32B per thread
    int4 rp[2];
    {
        const int4* src = reinterpret_cast<const int4*>(
            g_cbh + (size_t)ldn * DIM + ldq * 16);
        rp[0] = src[0]; rp[1] = src[1];
        int4* dst = reinterpret_cast<int4*>(cb_s + ldn * 72 + ldq * 16);
        dst[0] = rp[0]; dst[1] = rp[1];
    }
    __syncthreads();

    uint32_t acc[2][8][2];    // fp16x2 accumulators
    const int mi    = lane >> 3;
    const int arow0 = warp_m * 32 + (mi & 1) * 8 + (lane & 7);   // + mf*16
    const int acb0  = (mi >> 1) * 8;
    const int brow0 = warp_n * 64 + (lane & 7) + ((lane >> 4) & 1) * 8;  // + nb*16
    const int bklb  = ((lane >> 3) & 1) * 8;
    const int q     = lane >> 2;

    #pragma unroll 1
    for (int cc = 0; cc < 32; cc++) {
        const int ct = cc >> 2, kc = cc & 3, buf = cc & 1;
        if (kc == 0) {
            #pragma unroll
            for (int mf = 0; mf < 2; mf++)
                #pragma unroll
                for (int nf = 0; nf < 8; nf++) {
                    acc[mf][nf][0] = 0u; acc[mf][nf][1] = 0u;
                }
        }
        // prefetch next gmem chunk (cb is L2-hot, 512KB)
        if (cc < 31) {
            const int nct = (cc + 1) >> 2, nkc = (cc + 1) & 3;
            const int4* src = reinterpret_cast<const int4*>(
                g_cbh + (size_t)(nct * 128 + ldn) * DIM + nkc * 64 + ldq * 16);
            rp[0] = src[0]; rp[1] = src[1];
        }
        // mma over 4 k16 steps
        const __half* cbb = cb_s + buf * 9216;
        #pragma unroll
        for (int ks = 0; ks < 4; ks++) {
            const int ko = (kc * 4 + ks) * 16;
            uint32_t afr[2][4];
            #pragma unroll
            for (int mf = 0; mf < 2; mf++)
                LDSM_X4(afr[mf][0], afr[mf][1], afr[mf][2], afr[mf][3],
                        smaddr(z_s + (arow0 + mf * 16) * 264 + ko + acb0));
            uint32_t bfr[4][4];
            #pragma unroll
            for (int nb = 0; nb < 4; nb++)
                LDSM_X4(bfr[nb][0], bfr[nb][1], bfr[nb][2], bfr[nb][3],
                        smaddr(cbb + (brow0 + nb * 16) * 72 + ks * 16 + bklb));
            #pragma unroll
            for (int mf = 0; mf < 2; mf++)
                #pragma unroll
                for (int nb = 0; nb < 4; nb++) {
                    MMA16816H(acc[mf][2 * nb],     afr[mf], bfr[nb][0], bfr[nb][1]);
                    MMA16816H(acc[mf][2 * nb + 1], afr[mf], bfr[nb][2], bfr[nb][3]);
                }
        }
        // epilogue per code tile: running min + candidate collection
        if (kc == 3) {
            float rm[4] = {1.0e30f, 1.0e30f, 1.0e30f, 1.0e30f};
            #pragma unroll
            for (int mf = 0; mf < 2; mf++)
                #pragma unroll
                for (int nf = 0; nf < 8; nf++) {
                    int ng = ct * 128 + warp_n * 64 + nf * 8 + (lane & 3) * 2;
                    float cn0 = cn_s[ng], cn1 = cn_s[ng + 1];
                    float2 lo = __half22float2(
                        *reinterpret_cast<__half2*>(&acc[mf][nf][0]));
                    float2 hi = __half22float2(
                        *reinterpret_cast<__half2*>(&acc[mf][nf][1]));
                    rm[mf*2]   = fminf(rm[mf*2],   fminf(cn0 - 2.0f*lo.x,
                                                         cn1 - 2.0f*lo.y));
                    rm[mf*2+1] = fminf(rm[mf*2+1], fminf(cn0 - 2.0f*hi.x,
                                                         cn1 - 2.0f*hi.y));
                }
            #pragma unroll
            for (int i = 0; i < 4; i++) {
                rm[i] = fminf(rm[i], __shfl_xor_sync(~0u, rm[i], 1));
                rm[i] = fminf(rm[i], __shfl_xor_sync(~0u, rm[i], 2));
            }
            // row for slot i (= mf*2+half): warp_m*32 + q + i*8
            if ((lane & 3) == 0) {
                #pragma unroll
                for (int i = 0; i < 4; i++)
                    atomicMin(&rmin_s[warp_m * 32 + q + i * 8], enc_s(rm[i]));
            }
            float thr[4];
            #pragma unroll
            for (int i = 0; i < 4; i++)
                thr[i] = fminf(dec_s(rmin_s[warp_m * 32 + q + i * 8]), rm[i]) + EPSF;
            #pragma unroll
            for (int mf = 0; mf < 2; mf++)
                #pragma unroll
                for (int nf = 0; nf < 8; nf++) {
                    int ng = ct * 128 + warp_n * 64 + nf * 8 + (lane & 3) * 2;
                    float cn0 = cn_s[ng], cn1 = cn_s[ng + 1];
                    float2 lo = __half22float2(
                        *reinterpret_cast<__half2*>(&acc[mf][nf][0]));
                    float2 hi = __half22float2(
                        *reinterpret_cast<__half2*>(&acc[mf][nf][1]));
                    float s00 = cn0 - 2.0f * lo.x;
                    float s01 = cn1 - 2.0f * lo.y;
                    float s10 = cn0 - 2.0f * hi.x;
                    float s11 = cn1 - 2.0f * hi.y;
                    int rl = warp_m * 32 + q + mf * 16;
                    int rh = rl + 8;
                    if (s00 <= thr[mf*2]) { int p = atomicAdd(&cnt_s[rl], 1);
                        if (p < CAND_MAX) cand_s[rl * CAND_MAX + p] = (unsigned short)ng; }
                    if (s01 <= thr[mf*2]) { int p = atomicAdd(&cnt_s[rl], 1);
                        if (p < CAND_MAX) cand_s[rl * CAND_MAX + p] = (unsigned short)(ng + 1); }
                    if (s10 <= thr[mf*2+1]) { int p = atomicAdd(&cnt_s[rh], 1);
                        if (p < CAND_MAX) cand_s[rh * CAND_MAX + p] = (unsigned short)ng; }
                    if (s11 <= thr[mf*2+1]) { int p = atomicAdd(&cnt_s[rh], 1);
                        if (p < CAND_MAX) cand_s[rh * CAND_MAX + p] = (unsigned short)(ng + 1); }
                }
        }
        // store prefetched chunk into the other buffer (safe: its readers
        // finished at the previous barrier), then single barrier
        if (cc < 31) {
            int4* dst = reinterpret_cast<int4*>(
                cb_s + (buf ^ 1) * 9216 + ldn * 72 + ldq * 16);
            dst[0] = rp[0]; dst[1] = rp[1];
        }
        __syncthreads();
    }

    // ---- exact refine: warp w handles rows 16w..16w+15, flattened worklist ----
    {
        const int rb = wid * 16;
        int pre[16];
        int total = 0;
        #pragma unroll
        for (int r = 0; r < 16; r++) {
            pre[r] = total;
            int c = cnt_s[rb + r];
            total += (c > CAND_MAX) ? 0 : c;
        }
        for (int k = lane; k < total; k += 32) {
            int r = 0;
            #pragma unroll
            for (int t = 1; t < 16; t++) if (k >= pre[t]) r = t;
            int c  = (int)cand_s[(rb + r) * CAND_MAX + (k - pre[r])];
            int rg = r0g + rb + r;
            float d = exact_d(z, cb, rg, c, g_znorm[rg], cn_s[c]);
            unsigned long long key =
                ((unsigned long long)__float_as_uint(d) << 32) | (unsigned)c;
            atomicMin(&best_s[rb + r], key);
        }
        // rare overflow fallback: exact full scan
        for (int r = 0; r < 16; r++) {
            if (cnt_s[rb + r] > CAND_MAX) {
                int rg = r0g + rb + r;
                float zn = g_znorm[rg];
                for (int c = lane; c < NCODES; c += 32) {
                    float d = exact_d(z, cb, rg, c, zn, cn_s[c]);
                    unsigned long long key =
                        ((unsigned long long)__float_as_uint(d) << 32) | (unsigned)c;
                    atomicMin(&best_s[rb + r], key);
                }
            }
        }
        __syncwarp();
        if (lane < 16)
            g_codes[r0g + rb + lane] = (int)(best_s[rb + lane] & 0xFFFFFFFFu);
    }
}

// -------------------------------------------------------------------------
// Quantize: 2 independent streams, streaming stores, fused loss finalize.
// -------------------------------------------------------------------------
#define QHALF (N_ROWS * (DIM / 4) / 2)
__global__ void quantize_kernel(const float* __restrict__ z,
                                const float* __restrict__ cb,
                                float* __restrict__ out,
                                float* __restrict__ codes_out,
                                float* __restrict__ loss_out) {
    const int e0 = blockIdx.x * blockDim.x + threadIdx.x;
    float s = 0.0f;
    #pragma unroll
    for (int h = 0; h < 2; h++) {
        const int e = e0 + h * QHALF;
        const int row = e >> 6;
        const int col = e & 63;
        const int code = g_codes[row];
        float4 q4 = reinterpret_cast<const float4*>(cb + (size_t)code * DIM)[col];
        float4 z4 = reinterpret_cast<const float4*>(z)[e];
        float4 o4;
        o4.x = __fadd_rn(z4.x, __fsub_rn(q4.x, z4.x));
        o4.y = __fadd_rn(z4.y, __fsub_rn(q4.y, z4.y));
        o4.z = __fadd_rn(z4.z, __fsub_rn(q4.z, z4.z));
        o4.w = __fadd_rn(z4.w, __fsub_rn(q4.w, z4.w));
        __stcs(reinterpret_cast<float4*>(out) + e, o4);
        float dx = q4.x - z4.x, dy = q4.y - z4.y;
        float dz = q4.z - z4.z, dw = q4.w - z4.w;
        s += dx * dx + dy * dy + dz * dz + dw * dw;
    }
    if (codes_out && e0 < N_ROWS) codes_out[e0] = (float)g_codes[e0];

    #pragma unroll
    for (int off = 16; off > 0; off >>= 1)
        s += __shfl_down_sync(0xFFFFFFFFu, s, off);
    __shared__ float wsum[8];
    int lane = threadIdx.x & 31, warp = threadIdx.x >> 5;
    if (lane == 0) wsum[warp] = s;
    __syncthreads();
    if (threadIdx.x == 0) {
        float bs = 0.0f;
        #pragma unroll
        for (int w = 0; w < 8; w++) bs += wsum[w];
        atomicAdd(&g_loss_acc, (double)bs);
        __threadfence();
        unsigned t = atomicAdd(&g_done, 1u);
        if (t == gridDim.x - 1) {           // last block finalizes
            g_done = 0u;
            if (loss_out)
                *loss_out = (float)(1.25 * g_loss_acc /
                                    (double)((long long)N_ROWS * DIM));
        }
    }
}

// -------------------------------------------------------------------------
extern "C" void kernel_launch(void* const* d_in, const int* in_sizes, int n_in,
                              void* d_out, int out_size) {
    const float* z  = (const float*)d_in[0];
    const float* cb = (const float*)d_in[1];
    float* out = (float*)d_out;

    static bool attr_done = false;
    if (!attr_done) {
        cudaFuncSetAttribute(screen_kernel,
                             cudaFuncAttributeMaxDynamicSharedMemorySize, SMEM_SZ);
        attr_done = true;
    }

    prep_kernel<<<NCODES / 256, 256>>>(cb);
    znorm_kernel<<<N_ROWS / ZROWS, 256>>>(z);
    screen_kernel<<<N_ROWS / BM, NTHREADS, SMEM_SZ>>>(z, cb);

    const long long nd = (long long)N_ROWS * DIM;
    float* codes_out = (out_size >= (int)(nd + N_ROWS)) ? out + nd : nullptr;
    float* loss_out  = (out_size >= (int)(nd + N_ROWS + 1)) ? out + nd + N_ROWS
                                                            : nullptr;
    quantize_kernel<<<QHALF / 256, 256>>>(z, cb, out, codes_out, loss_out);
}

// round 16
// speedup vs baseline: 1.2972x; 1.2972x over previous
#include <cuda_runtime.h>
#include <cuda_fp16.h>
#include <cstdint>

#define N_ROWS 65536
#define DIM    256
#define NCODES 1024
#define BM     128
#define NTHREADS 256
#define EPSF   1.0e-3f
#define CAND_MAX 16

__device__ float    g_cnorm[NCODES];
__device__ float    g_znorm[N_ROWS];
__device__ int      g_codes[N_ROWS];
__device__ double   g_loss_acc;
__device__ unsigned g_done;
__device__ __half   g_cbh[NCODES * DIM];

// ---- smem layout (bytes), total 114688 -> 2 CTAs/SM (229376 <= 228KB) ----
#define O_ZS   0                 // [128] rows x 264-half pitch = 67584
#define O_CBS  67584             // 2 x [128][72] half = 2 x 18432 = 36864
#define O_CN   104448            // [1024] float = 4096
#define O_RMIN 108544            // [128] uint = 512
#define O_CNT  109056            // [128] int = 512
#define O_CAND 109568            // [128][16] u16 = 4096
#define O_BEST 113664            // [128] u64 = 1024
#define SMEM_SZ 114688

__device__ __forceinline__ uint32_t smaddr(const void* p) {
    return (uint32_t)__cvta_generic_to_shared(p);
}
#define LDSM_X4(r0,r1,r2,r3,a) \
    asm volatile("ldmatrix.sync.aligned.m8n8.x4.shared.b16 {%0,%1,%2,%3}, [%4];" \
        : "=r"(r0),"=r"(r1),"=r"(r2),"=r"(r3) : "r"(a))
#define MMA16816(d,a,b0,b1) \
    asm volatile("mma.sync.aligned.m16n8k16.row.col.f32.f16.f16.f32 " \
        "{%0,%1,%2,%3},{%4,%5,%6,%7},{%8,%9},{%0,%1,%2,%3};" \
        : "+f"(d[0]),"+f"(d[1]),"+f"(d[2]),"+f"(d[3]) \
        : "r"(a[0]),"r"(a[1]),"r"(a[2]),"r"(a[3]),"r"(b0),"r"(b1))

// monotone encode for floats in (-1,1): s+1 > 0
__device__ __forceinline__ uint32_t enc_s(float s) { return __float_as_uint(s + 1.0f); }
__device__ __forceinline__ float dec_s(uint32_t u) { return __uint_as_float(u) - 1.0f; }

// exact reference-rounding distance: d = fl(fl(zn+cn) - fl(2*dot)),
// dot = sequential ascending-d fp32 FMA chain.
__device__ __forceinline__ float exact_d(const float* __restrict__ z,
                                         const float* __restrict__ cb,
                                         int rg, int c, float zn, float cn) {
    const float4* zp = reinterpret_cast<const float4*>(z + (size_t)rg * DIM);
    const float4* cp = reinterpret_cast<const float4*>(cb + (size_t)c * DIM);
    float dot = 0.0f;
    #pragma unroll 8
    for (int t = 0; t < DIM / 4; t++) {
        float4 zv = __ldg(zp + t);
        float4 cv = __ldg(cp + t);
        dot = __fmaf_rn(zv.x, cv.x, dot);
        dot = __fmaf_rn(zv.y, cv.y, dot);
        dot = __fmaf_rn(zv.z, cv.z, dot);
        dot = __fmaf_rn(zv.w, cv.w, dot);
    }
    return __fsub_rn(__fadd_rn(zn, cn), __fmul_rn(2.0f, dot));
}

// -------------------------------------------------------------------------
// Prep: codebook norms + codebook fp16 (strict in-order rounding) + zero accs.
// -------------------------------------------------------------------------
__global__ void prep_kernel(const float* __restrict__ cb) {
    int i = blockIdx.x * blockDim.x + threadIdx.x;   // 0..1023
    if (i == 0) { g_loss_acc = 0.0; g_done = 0u; }
    const float4* row = reinterpret_cast<const float4*>(cb + (size_t)i * DIM);
    __half2* dst = reinterpret_cast<__half2*>(g_cbh + (size_t)i * DIM);
    float s = 0.0f;
    #pragma unroll
    for (int t = 0; t < DIM / 4; t++) {
        float4 v = row[t];
        s = __fadd_rn(s, __fmul_rn(v.x, v.x));
        s = __fadd_rn(s, __fmul_rn(v.y, v.y));
        s = __fadd_rn(s, __fmul_rn(v.z, v.z));
        s = __fadd_rn(s, __fmul_rn(v.w, v.w));
        dst[2 * t]     = __floats2half2_rn(v.x, v.y);
        dst[2 * t + 1] = __floats2half2_rn(v.z, v.w);
    }
    g_cnorm[i] = s;
}

// -------------------------------------------------------------------------
// Coalesced z row norms: stage 32 rows via smem, then 32 in-order chains.
// -------------------------------------------------------------------------
#define ZROWS 32
__global__ void znorm_kernel(const float* __restrict__ z) {
    __shared__ float buf[ZROWS][DIM + 1];   // pitch 257 -> conflict-free
    const int tid = threadIdx.x;
    const int r0  = blockIdx.x * ZROWS;

    #pragma unroll
    for (int k = 0; k < (ZROWS * DIM / 4) / 256; k++) {
        int i = tid + k * 256;
        int row = i >> 6, c4 = i & 63;
        float4 v = __ldg(reinterpret_cast<const float4*>(
            z + (size_t)(r0 + row) * DIM) + c4);
        buf[row][c4 * 4 + 0] = v.x;
        buf[row][c4 * 4 + 1] = v.y;
        buf[row][c4 * 4 + 2] = v.z;
        buf[row][c4 * 4 + 3] = v.w;
    }
    __syncthreads();

    if (tid < ZROWS) {
        float s = 0.0f;
        #pragma unroll 8
        for (int i = 0; i < DIM; i++)
            s = __fadd_rn(s, __fmul_rn(buf[tid][i], buf[tid][i]));
        g_znorm[r0 + tid] = s;
    }
}

// -------------------------------------------------------------------------
// Screen: fp16 mma (warp tile 32x64, 8 warps/CTA, BM=128, 2 CTAs/SM)
// + fused running-min candidate collection + exact fp32-chain refine.
// -------------------------------------------------------------------------
__global__ __launch_bounds__(NTHREADS, 2)
void screen_kernel(const float* __restrict__ z, const float* __restrict__ cb) {
    extern __shared__ unsigned char sm[];
    __half* z_s  = reinterpret_cast<__half*>(sm + O_ZS);
    __half* cb_s = reinterpret_cast<__half*>(sm + O_CBS);
    float*  cn_s = reinterpret_cast<float*>(sm + O_CN);
    uint32_t* rmin_s = reinterpret_cast<uint32_t*>(sm + O_RMIN);
    int* cnt_s = reinterpret_cast<int*>(sm + O_CNT);
    unsigned short* cand_s = reinterpret_cast<unsigned short*>(sm + O_CAND);
    unsigned long long* best_s = reinterpret_cast<unsigned long long*>(sm + O_BEST);

    const int tid  = threadIdx.x;
    const int lane = tid & 31;
    const int wid  = tid >> 5;
    const int warp_m = wid & 3;   // rows warp_m*32..+31
    const int warp_n = wid >> 2;  // codes warp_n*64..+63
    const int r0g = blockIdx.x * BM;

    // ---- init + load z tile (fp32 -> fp16 convert) + cn ----
    {
        const int zrow = tid >> 1, zh = tid & 1;
        const float4* zsrc = reinterpret_cast<const float4*>(
            z + (size_t)(r0g + zrow) * DIM + zh * 128);
        __half2* zdst = reinterpret_cast<__half2*>(z_s + zrow * 264 + zh * 128);
        #pragma unroll 8
        for (int t = 0; t < 32; t++) {
            float4 v = zsrc[t];
            zdst[2 * t]     = __floats2half2_rn(v.x, v.y);
            zdst[2 * t + 1] = __floats2half2_rn(v.z, v.w);
        }
        reinterpret_cast<float4*>(cn_s)[tid] =
            reinterpret_cast<const float4*>(g_cnorm)[tid];
        if (tid < BM) {
            rmin_s[tid] = __float_as_uint(100.0f);
            cnt_s[tid] = 0;
            best_s[tid] = 0xFFFFFFFFFFFFFFFFull;
        }
    }

    // B chunk loader mapping (128 codes x 64 dims fp16 per chunk, 16KB)
    const int ldn = tid >> 1, ldh = tid & 1;   // 64B per thread
    int4 rp[4];
    {
        const int4* src = reinterpret_cast<const int4*>(
            g_cbh + (size_t)ldn * DIM + ldh * 32);
        #pragma unroll
        for (int t = 0; t < 4; t++) rp[t] = src[t];
        int4* dst = reinterpret_cast<int4*>(cb_s + ldn * 72 + ldh * 32);
        #pragma unroll
        for (int t = 0; t < 4; t++) dst[t] = rp[t];
    }
    __syncthreads();

    float acc[2][8][4];
    const int mi    = lane >> 3;
    const int arow0 = warp_m * 32 + (mi & 1) * 8 + (lane & 7);   // + mf*16
    const int acb0  = (mi >> 1) * 8;
    const int brow0 = warp_n * 64 + (lane & 7) + ((lane >> 4) & 1) * 8;  // + nb*16
    const int bklb  = ((lane >> 3) & 1) * 8;
    const int q     = lane >> 2;

    #pragma unroll 1
    for (int cc = 0; cc < 32; cc++) {
        const int ct = cc >> 2, kc = cc & 3, buf = cc & 1;
        if (kc == 0) {
            #pragma unroll
            for (int mf = 0; mf < 2; mf++)
                #pragma unroll
                for (int nf = 0; nf < 8; nf++)
                    #pragma unroll
                    for (int j = 0; j < 4; j++) acc[mf][nf][j] = 0.0f;
        }
        // prefetch next gmem chunk (cb is L2-hot, 512KB)
        if (cc < 31) {
            const int nct = (cc + 1) >> 2, nkc = (cc + 1) & 3;
            const int4* src = reinterpret_cast<const int4*>(
                g_cbh + (size_t)(nct * 128 + ldn) * DIM + nkc * 64 + ldh * 32);
            #pragma unroll
            for (int t = 0; t < 4; t++) rp[t] = src[t];
        }
        // mma over 4 k16 steps
        const __half* cbb = cb_s + buf * 9216;
        #pragma unroll
        for (int ks = 0; ks < 4; ks++) {
            const int ko = (kc * 4 + ks) * 16;
            uint32_t afr[2][4];
            #pragma unroll
            for (int mf = 0; mf < 2; mf++)
                LDSM_X4(afr[mf][0], afr[mf][1], afr[mf][2], afr[mf][3],
                        smaddr(z_s + (arow0 + mf * 16) * 264 + ko + acb0));
            uint32_t bfr[4][4];
            #pragma unroll
            for (int nb = 0; nb < 4; nb++)
                LDSM_X4(bfr[nb][0], bfr[nb][1], bfr[nb][2], bfr[nb][3],
                        smaddr(cbb + (brow0 + nb * 16) * 72 + ks * 16 + bklb));
            #pragma unroll
            for (int mf = 0; mf < 2; mf++)
                #pragma unroll
                for (int nb = 0; nb < 4; nb++) {
                    MMA16816(acc[mf][2 * nb],     afr[mf], bfr[nb][0], bfr[nb][1]);
                    MMA16816(acc[mf][2 * nb + 1], afr[mf], bfr[nb][2], bfr[nb][3]);
                }
        }
        // epilogue per code tile: running min + candidate collection
        if (kc == 3) {
            float rm[4] = {1.0e30f, 1.0e30f, 1.0e30f, 1.0e30f};
            #pragma unroll
            for (int mf = 0; mf < 2; mf++)
                #pragma unroll
                for (int nf = 0; nf < 8; nf++) {
                    int ng = ct * 128 + warp_n * 64 + nf * 8 + (lane & 3) * 2;
                    float cn0 = cn_s[ng], cn1 = cn_s[ng + 1];
                    rm[mf*2]   = fminf(rm[mf*2],   fminf(cn0 - 2.0f*acc[mf][nf][0],
                                                         cn1 - 2.0f*acc[mf][nf][1]));
                    rm[mf*2+1] = fminf(rm[mf*2+1], fminf(cn0 - 2.0f*acc[mf][nf][2],
                                                         cn1 - 2.0f*acc[mf][nf][3]));
                }
            #pragma unroll
            for (int i = 0; i < 4; i++) {
                rm[i] = fminf(rm[i], __shfl_xor_sync(~0u, rm[i], 1));
                rm[i] = fminf(rm[i], __shfl_xor_sync(~0u, rm[i], 2));
            }
            // row for slot i (= mf*2+half): warp_m*32 + q + i*8
            if ((lane & 3) == 0) {
                #pragma unroll
                for (int i = 0; i < 4; i++)
                    atomicMin(&rmin_s[warp_m * 32 + q + i * 8], enc_s(rm[i]));
            }
            float thr[4];
            #pragma unroll
            for (int i = 0; i < 4; i++)
                thr[i] = fminf(dec_s(rmin_s[warp_m * 32 + q + i * 8]), rm[i]) + EPSF;
            #pragma unroll
            for (int mf = 0; mf < 2; mf++)
                #pragma unroll
                for (int nf = 0; nf < 8; nf++) {
                    int ng = ct * 128 + warp_n * 64 + nf * 8 + (lane & 3) * 2;
                    float cn0 = cn_s[ng], cn1 = cn_s[ng + 1];
                    float s00 = cn0 - 2.0f * acc[mf][nf][0];
                    float s01 = cn1 - 2.0f * acc[mf][nf][1];
                    float s10 = cn0 - 2.0f * acc[mf][nf][2];
                    float s11 = cn1 - 2.0f * acc[mf][nf][3];
                    int rl = warp_m * 32 + q + mf * 16;
                    int rh = rl + 8;
                    if (s00 <= thr[mf*2]) { int p = atomicAdd(&cnt_s[rl], 1);
                        if (p < CAND_MAX) cand_s[rl * CAND_MAX + p] = (unsigned short)ng; }
                    if (s01 <= thr[mf*2]) { int p = atomicAdd(&cnt_s[rl], 1);
                        if (p < CAND_MAX) cand_s[rl * CAND_MAX + p] = (unsigned short)(ng + 1); }
                    if (s10 <= thr[mf*2+1]) { int p = atomicAdd(&cnt_s[rh], 1);
                        if (p < CAND_MAX) cand_s[rh * CAND_MAX + p] = (unsigned short)ng; }
                    if (s11 <= thr[mf*2+1]) { int p = atomicAdd(&cnt_s[rh], 1);
                        if (p < CAND_MAX) cand_s[rh * CAND_MAX + p] = (unsigned short)(ng + 1); }
                }
        }
        // store prefetched chunk into the other buffer (safe: its readers
        // finished at the previous barrier), then single barrier
        if (cc < 31) {
            int4* dst = reinterpret_cast<int4*>(
                cb_s + (buf ^ 1) * 9216 + ldn * 72 + ldh * 32);
            #pragma unroll
            for (int t = 0; t < 4; t++) dst[t] = rp[t];
        }
        __syncthreads();
    }

    // ---- exact refine: warp w handles rows 16w..16w+15, flattened worklist ----
    {
        const int rb = wid * 16;
        int pre[16];
        int total = 0;
        #pragma unroll
        for (int r = 0; r < 16; r++) {
            pre[r] = total;
            int c = cnt_s[rb + r];
            total += (c > CAND_MAX) ? 0 : c;
        }
        for (int k = lane; k < total; k += 32) {
            int r = 0;
            #pragma unroll
            for (int t = 1; t < 16; t++) if (k >= pre[t]) r = t;
            int c  = (int)cand_s[(rb + r) * CAND_MAX + (k - pre[r])];
            int rg = r0g + rb + r;
            float d = exact_d(z, cb, rg, c, g_znorm[rg], cn_s[c]);
            unsigned long long key =
                ((unsigned long long)__float_as_uint(d) << 32) | (unsigned)c;
            atomicMin(&best_s[rb + r], key);
        }
        // rare overflow fallback: exact full scan
        for (int r = 0; r < 16; r++) {
            if (cnt_s[rb + r] > CAND_MAX) {
                int rg = r0g + rb + r;
                float zn = g_znorm[rg];
                for (int c = lane; c < NCODES; c += 32) {
                    float d = exact_d(z, cb, rg, c, zn, cn_s[c]);
                    unsigned long long key =
                        ((unsigned long long)__float_as_uint(d) << 32) | (unsigned)c;
                    atomicMin(&best_s[rb + r], key);
                }
            }
        }
        __syncwarp();
        if (lane < 16)
            g_codes[r0g + rb + lane] = (int)(best_s[rb + lane] & 0xFFFFFFFFu);
    }
}

// -------------------------------------------------------------------------
// Quantize: 2 independent streams, streaming stores, fused loss finalize.
// -------------------------------------------------------------------------
#define QHALF (N_ROWS * (DIM / 4) / 2)
__global__ void quantize_kernel(const float* __restrict__ z,
                                const float* __restrict__ cb,
                                float* __restrict__ out,
                                float* __restrict__ codes_out,
                                float* __restrict__ loss_out) {
    const int e0 = blockIdx.x * blockDim.x + threadIdx.x;
    float s = 0.0f;
    #pragma unroll
    for (int h = 0; h < 2; h++) {
        const int e = e0 + h * QHALF;
        const int row = e >> 6;
        const int col = e & 63;
        const int code = g_codes[row];
        float4 q4 = reinterpret_cast<const float4*>(cb + (size_t)code * DIM)[col];
        float4 z4 = reinterpret_cast<const float4*>(z)[e];
        float4 o4;
        o4.x = __fadd_rn(z4.x, __fsub_rn(q4.x, z4.x));
        o4.y = __fadd_rn(z4.y, __fsub_rn(q4.y, z4.y));
        o4.z = __fadd_rn(z4.z, __fsub_rn(q4.z, z4.z));
        o4.w = __fadd_rn(z4.w, __fsub_rn(q4.w, z4.w));
        __stcs(reinterpret_cast<float4*>(out) + e, o4);
        float dx = q4.x - z4.x, dy = q4.y - z4.y;
        float dz = q4.z - z4.z, dw = q4.w - z4.w;
        s += dx * dx + dy * dy + dz * dz + dw * dw;
    }
    if (codes_out && e0 < N_ROWS) codes_out[e0] = (float)g_codes[e0];

    #pragma unroll
    for (int off = 16; off > 0; off >>= 1)
        s += __shfl_down_sync(0xFFFFFFFFu, s, off);
    __shared__ float wsum[8];
    int lane = threadIdx.x & 31, warp = threadIdx.x >> 5;
    if (lane == 0) wsum[warp] = s;
    __syncthreads();
    if (threadIdx.x == 0) {
        float bs = 0.0f;
        #pragma unroll
        for (int w = 0; w < 8; w++) bs += wsum[w];
        atomicAdd(&g_loss_acc, (double)bs);
        __threadfence();
        unsigned t = atomicAdd(&g_done, 1u);
        if (t == gridDim.x - 1) {           // last block finalizes
            g_done = 0u;
            if (loss_out)
                *loss_out = (float)(1.25 * g_loss_acc /
                                    (double)((long long)N_ROWS * DIM));
        }
    }
}

// -------------------------------------------------------------------------
extern "C" void kernel_launch(void* const* d_in, const int* in_sizes, int n_in,
                              void* d_out, int out_size) {
    const float* z  = (const float*)d_in[0];
    const float* cb = (const float*)d_in[1];
    float* out = (float*)d_out;

    static bool attr_done = false;
    if (!attr_done) {
        cudaFuncSetAttribute(screen_kernel,
                             cudaFuncAttributeMaxDynamicSharedMemorySize, SMEM_SZ);
        attr_done = true;
    }

    prep_kernel<<<NCODES / 256, 256>>>(cb);
    znorm_kernel<<<N_ROWS / ZROWS, 256>>>(z);
    screen_kernel<<<N_ROWS / BM, NTHREADS, SMEM_SZ>>>(z, cb);

    const long long nd = (long long)N_ROWS * DIM;
    float* codes_out = (out_size >= (int)(nd + N_ROWS)) ? out + nd : nullptr;
    float* loss_out  = (out_size >= (int)(nd + N_ROWS + 1)) ? out + nd + N_ROWS
                                                            : nullptr;
    quantize_kernel<<<QHALF / 256, 256>>>(z, cb, out, codes_out, loss_out);
}

// round 17
// speedup vs baseline: 1.4190x; 1.0939x over previous
#include <cuda_runtime.h>
#include <cuda_fp16.h>
#include <cstdint>

#define N_ROWS 65536
#define DIM    256
#define NCODES 1024
#define BM     256
#define NTHREADS 512
#define EPSF   1.0e-3f
#define CAND_MAX 32

__device__ float    g_cnorm[NCODES];
__device__ float    g_znorm[N_ROWS];
__device__ double   g_loss_acc;
__device__ unsigned g_done;
__device__ __half   g_cbh[NCODES * DIM];

// ---- smem layout (bytes) ----
#define O_ZS   0                 // [256] rows x 264-half pitch = 135168
#define O_CBS  135168            // 2 x [128][72] half = 36864
#define O_CN   172032            // [1024] float = 4096
#define O_RMIN 176128            // [256] uint = 1024
#define O_CNT  177152            // [256] int = 1024
#define O_CAND 178176            // [256][32] u16 = 16384
#define O_BEST 194560            // [256] u64 = 2048
#define SMEM_SZ 196608

__device__ __forceinline__ uint32_t smaddr(const void* p) {
    return (uint32_t)__cvta_generic_to_shared(p);
}
#define LDSM_X4(r0,r1,r2,r3,a) \
    asm volatile("ldmatrix.sync.aligned.m8n8.x4.shared.b16 {%0,%1,%2,%3}, [%4];" \
        : "=r"(r0),"=r"(r1),"=r"(r2),"=r"(r3) : "r"(a))
#define MMA16816(d,a,b0,b1) \
    asm volatile("mma.sync.aligned.m16n8k16.row.col.f32.f16.f16.f32 " \
        "{%0,%1,%2,%3},{%4,%5,%6,%7},{%8,%9},{%0,%1,%2,%3};" \
        : "+f"(d[0]),"+f"(d[1]),"+f"(d[2]),"+f"(d[3]) \
        : "r"(a[0]),"r"(a[1]),"r"(a[2]),"r"(a[3]),"r"(b0),"r"(b1))

// monotone encode for floats in (-1,1): s+1 > 0
__device__ __forceinline__ uint32_t enc_s(float s) { return __float_as_uint(s + 1.0f); }
__device__ __forceinline__ float dec_s(uint32_t u) { return __uint_as_float(u) - 1.0f; }

// exact reference-rounding distance: d = fl(fl(zn+cn) - fl(2*dot)),
// dot = sequential ascending-d fp32 FMA chain.
__device__ __forceinline__ float exact_d(const float* __restrict__ z,
                                         const float* __restrict__ cb,
                                         int rg, int c, float zn, float cn) {
    const float4* zp = reinterpret_cast<const float4*>(z + (size_t)rg * DIM);
    const float4* cp = reinterpret_cast<const float4*>(cb + (size_t)c * DIM);
    float dot = 0.0f;
    #pragma unroll 8
    for (int t = 0; t < DIM / 4; t++) {
        float4 zv = __ldg(zp + t);
        float4 cv = __ldg(cp + t);
        dot = __fmaf_rn(zv.x, cv.x, dot);
        dot = __fmaf_rn(zv.y, cv.y, dot);
        dot = __fmaf_rn(zv.z, cv.z, dot);
        dot = __fmaf_rn(zv.w, cv.w, dot);
    }
    return __fsub_rn(__fadd_rn(zn, cn), __fmul_rn(2.0f, dot));
}

// -------------------------------------------------------------------------
// Prep: codebook norms + codebook fp16 (strict in-order rounding) + zero accs.
// -------------------------------------------------------------------------
__global__ void prep_kernel(const float* __restrict__ cb) {
    int i = blockIdx.x * blockDim.x + threadIdx.x;   // 0..1023
    if (i == 0) { g_loss_acc = 0.0; g_done = 0u; }
    const float4* row = reinterpret_cast<const float4*>(cb + (size_t)i * DIM);
    __half2* dst = reinterpret_cast<__half2*>(g_cbh + (size_t)i * DIM);
    float s = 0.0f;
    #pragma unroll
    for (int t = 0; t < DIM / 4; t++) {
        float4 v = row[t];
        s = __fadd_rn(s, __fmul_rn(v.x, v.x));
        s = __fadd_rn(s, __fmul_rn(v.y, v.y));
        s = __fadd_rn(s, __fmul_rn(v.z, v.z));
        s = __fadd_rn(s, __fmul_rn(v.w, v.w));
        dst[2 * t]     = __floats2half2_rn(v.x, v.y);
        dst[2 * t + 1] = __floats2half2_rn(v.z, v.w);
    }
    g_cnorm[i] = s;
}

// -------------------------------------------------------------------------
// Coalesced z row norms: stage 32 rows via smem, then 32 in-order chains.
// -------------------------------------------------------------------------
#define ZROWS 32
__global__ void znorm_kernel(const float* __restrict__ z) {
    __shared__ float buf[ZROWS][DIM + 1];   // pitch 257 -> conflict-free
    const int tid = threadIdx.x;
    const int r0  = blockIdx.x * ZROWS;

    #pragma unroll
    for (int k = 0; k < (ZROWS * DIM / 4) / 256; k++) {
        int i = tid + k * 256;
        int row = i >> 6, c4 = i & 63;
        float4 v = __ldg(reinterpret_cast<const float4*>(
            z + (size_t)(r0 + row) * DIM) + c4);
        buf[row][c4 * 4 + 0] = v.x;
        buf[row][c4 * 4 + 1] = v.y;
        buf[row][c4 * 4 + 2] = v.z;
        buf[row][c4 * 4 + 3] = v.w;
    }
    __syncthreads();

    if (tid < ZROWS) {
        float s = 0.0f;
        #pragma unroll 8
        for (int i = 0; i < DIM; i++)
            s = __fadd_rn(s, __fmul_rn(buf[tid][i], buf[tid][i]));
        g_znorm[r0 + tid] = s;
    }
}

// -------------------------------------------------------------------------
// Screen: fp16 mma (warp tile 32x64, 16 warps/CTA, BM=256) + fused
// running-min candidate collection + exact fp32-chain refine + FUSED
// quantize/STE/loss tail (overlaps with other CTAs' MMA phases).
// -------------------------------------------------------------------------
__global__ __launch_bounds__(NTHREADS, 1)
void screen_kernel(const float* __restrict__ z, const float* __restrict__ cb,
                   float* __restrict__ out, float* __restrict__ codes_out,
                   float* __restrict__ loss_out) {
    extern __shared__ unsigned char sm[];
    __half* z_s  = reinterpret_cast<__half*>(sm + O_ZS);
    __half* cb_s = reinterpret_cast<__half*>(sm + O_CBS);
    float*  cn_s = reinterpret_cast<float*>(sm + O_CN);
    uint32_t* rmin_s = reinterpret_cast<uint32_t*>(sm + O_RMIN);
    int* cnt_s = reinterpret_cast<int*>(sm + O_CNT);
    unsigned short* cand_s = reinterpret_cast<unsigned short*>(sm + O_CAND);
    unsigned long long* best_s = reinterpret_cast<unsigned long long*>(sm + O_BEST);

    const int tid  = threadIdx.x;
    const int lane = tid & 31;
    const int wid  = tid >> 5;
    const int warp_m = wid & 7;   // rows warp_m*32..+31
    const int warp_n = wid >> 3;  // codes warp_n*64..+63
    const int r0g = blockIdx.x * BM;

    // ---- init + load z tile (fp32 -> fp16 convert) + cn ----
    {
        const int zrow = tid >> 1, zh = tid & 1;
        const float4* zsrc = reinterpret_cast<const float4*>(
            z + (size_t)(r0g + zrow) * DIM + zh * 128);
        __half2* zdst = reinterpret_cast<__half2*>(z_s + zrow * 264 + zh * 128);
        #pragma unroll 8
        for (int t = 0; t < 32; t++) {
            float4 v = zsrc[t];
            zdst[2 * t]     = __floats2half2_rn(v.x, v.y);
            zdst[2 * t + 1] = __floats2half2_rn(v.z, v.w);
        }
        if (tid < 256)
            reinterpret_cast<float4*>(cn_s)[tid] =
                reinterpret_cast<const float4*>(g_cnorm)[tid];
        if (tid < BM) {
            rmin_s[tid] = __float_as_uint(100.0f);
            cnt_s[tid] = 0;
            best_s[tid] = 0xFFFFFFFFFFFFFFFFull;
        }
    }

    // B chunk loader mapping (128 codes x 64 dims fp16 per chunk, 16KB)
    const int ldn = tid >> 2, ldq = tid & 3;   // 32B per thread
    int4 rp[2];
    {
        const int4* src = reinterpret_cast<const int4*>(
            g_cbh + (size_t)ldn * DIM + ldq * 16);
        rp[0] = src[0]; rp[1] = src[1];
        int4* dst = reinterpret_cast<int4*>(cb_s + ldn * 72 + ldq * 16);
        dst[0] = rp[0]; dst[1] = rp[1];
    }
    __syncthreads();

    float acc[2][8][4];
    const int mi    = lane >> 3;
    const int arow0 = warp_m * 32 + (mi & 1) * 8 + (lane & 7);   // + mf*16
    const int acb0  = (mi >> 1) * 8;
    const int brow0 = warp_n * 64 + (lane & 7) + ((lane >> 4) & 1) * 8;  // + nb*16
    const int bklb  = ((lane >> 3) & 1) * 8;
    const int q     = lane >> 2;

    #pragma unroll 1
    for (int cc = 0; cc < 32; cc++) {
        const int ct = cc >> 2, kc = cc & 3, buf = cc & 1;
        if (kc == 0) {
            #pragma unroll
            for (int mf = 0; mf < 2; mf++)
                #pragma unroll
                for (int nf = 0; nf < 8; nf++)
                    #pragma unroll
                    for (int j = 0; j < 4; j++) acc[mf][nf][j] = 0.0f;
        }
        // prefetch next gmem chunk (cb is L2-hot, 512KB)
        if (cc < 31) {
            const int nct = (cc + 1) >> 2, nkc = (cc + 1) & 3;
            const int4* src = reinterpret_cast<const int4*>(
                g_cbh + (size_t)(nct * 128 + ldn) * DIM + nkc * 64 + ldq * 16);
            rp[0] = src[0]; rp[1] = src[1];
        }
        // mma over 4 k16 steps
        const __half* cbb = cb_s + buf * 9216;
        #pragma unroll
        for (int ks = 0; ks < 4; ks++) {
            const int ko = (kc * 4 + ks) * 16;
            uint32_t afr[2][4];
            #pragma unroll
            for (int mf = 0; mf < 2; mf++)
                LDSM_X4(afr[mf][0], afr[mf][1], afr[mf][2], afr[mf][3],
                        smaddr(z_s + (arow0 + mf * 16) * 264 + ko + acb0));
            uint32_t bfr[4][4];
            #pragma unroll
            for (int nb = 0; nb < 4; nb++)
                LDSM_X4(bfr[nb][0], bfr[nb][1], bfr[nb][2], bfr[nb][3],
                        smaddr(cbb + (brow0 + nb * 16) * 72 + ks * 16 + bklb));
            #pragma unroll
            for (int mf = 0; mf < 2; mf++)
                #pragma unroll
                for (int nb = 0; nb < 4; nb++) {
                    MMA16816(acc[mf][2 * nb],     afr[mf], bfr[nb][0], bfr[nb][1]);
                    MMA16816(acc[mf][2 * nb + 1], afr[mf], bfr[nb][2], bfr[nb][3]);
                }
        }
        // epilogue per code tile: running min + candidate collection
        if (kc == 3) {
            float rm[4] = {1.0e30f, 1.0e30f, 1.0e30f, 1.0e30f};
            #pragma unroll
            for (int mf = 0; mf < 2; mf++)
                #pragma unroll
                for (int nf = 0; nf < 8; nf++) {
                    int ng = ct * 128 + warp_n * 64 + nf * 8 + (lane & 3) * 2;
                    float cn0 = cn_s[ng], cn1 = cn_s[ng + 1];
                    rm[mf*2]   = fminf(rm[mf*2],   fminf(cn0 - 2.0f*acc[mf][nf][0],
                                                         cn1 - 2.0f*acc[mf][nf][1]));
                    rm[mf*2+1] = fminf(rm[mf*2+1], fminf(cn0 - 2.0f*acc[mf][nf][2],
                                                         cn1 - 2.0f*acc[mf][nf][3]));
                }
            #pragma unroll
            for (int i = 0; i < 4; i++) {
                rm[i] = fminf(rm[i], __shfl_xor_sync(~0u, rm[i], 1));
                rm[i] = fminf(rm[i], __shfl_xor_sync(~0u, rm[i], 2));
            }
            // row for slot i (= mf*2+half): warp_m*32 + q + i*8
            if ((lane & 3) == 0) {
                #pragma unroll
                for (int i = 0; i < 4; i++)
                    atomicMin(&rmin_s[warp_m * 32 + q + i * 8], enc_s(rm[i]));
            }
            float thr[4];
            #pragma unroll
            for (int i = 0; i < 4; i++)
                thr[i] = fminf(dec_s(rmin_s[warp_m * 32 + q + i * 8]), rm[i]) + EPSF;
            #pragma unroll
            for (int mf = 0; mf < 2; mf++)
                #pragma unroll
                for (int nf = 0; nf < 8; nf++) {
                    int ng = ct * 128 + warp_n * 64 + nf * 8 + (lane & 3) * 2;
                    float cn0 = cn_s[ng], cn1 = cn_s[ng + 1];
                    float s00 = cn0 - 2.0f * acc[mf][nf][0];
                    float s01 = cn1 - 2.0f * acc[mf][nf][1];
                    float s10 = cn0 - 2.0f * acc[mf][nf][2];
                    float s11 = cn1 - 2.0f * acc[mf][nf][3];
                    int rl = warp_m * 32 + q + mf * 16;
                    int rh = rl + 8;
                    if (s00 <= thr[mf*2]) { int p = atomicAdd(&cnt_s[rl], 1);
                        if (p < CAND_MAX) cand_s[rl * CAND_MAX + p] = (unsigned short)ng; }
                    if (s01 <= thr[mf*2]) { int p = atomicAdd(&cnt_s[rl], 1);
                        if (p < CAND_MAX) cand_s[rl * CAND_MAX + p] = (unsigned short)(ng + 1); }
                    if (s10 <= thr[mf*2+1]) { int p = atomicAdd(&cnt_s[rh], 1);
                        if (p < CAND_MAX) cand_s[rh * CAND_MAX + p] = (unsigned short)ng; }
                    if (s11 <= thr[mf*2+1]) { int p = atomicAdd(&cnt_s[rh], 1);
                        if (p < CAND_MAX) cand_s[rh * CAND_MAX + p] = (unsigned short)(ng + 1); }
                }
        }
        // store prefetched chunk into the other buffer (safe: its readers
        // finished at the previous barrier), then single barrier
        if (cc < 31) {
            int4* dst = reinterpret_cast<int4*>(
                cb_s + (buf ^ 1) * 9216 + ldn * 72 + ldq * 16);
            dst[0] = rp[0]; dst[1] = rp[1];
        }
        __syncthreads();
    }

    // ---- exact refine: warp w handles rows 16w..16w+15, flattened worklist ----
    {
        const int rb = wid * 16;
        int pre[16];
        int total = 0;
        #pragma unroll
        for (int r = 0; r < 16; r++) {
            pre[r] = total;
            int c = cnt_s[rb + r];
            total += (c > CAND_MAX) ? 0 : c;
        }
        for (int k = lane; k < total; k += 32) {
            int r = 0;
            #pragma unroll
            for (int t = 1; t < 16; t++) if (k >= pre[t]) r = t;
            int c  = (int)cand_s[(rb + r) * CAND_MAX + (k - pre[r])];
            int rg = r0g + rb + r;
            float d = exact_d(z, cb, rg, c, g_znorm[rg], cn_s[c]);
            unsigned long long key =
                ((unsigned long long)__float_as_uint(d) << 32) | (unsigned)c;
            atomicMin(&best_s[rb + r], key);
        }
        // rare overflow fallback: exact full scan
        for (int r = 0; r < 16; r++) {
            if (cnt_s[rb + r] > CAND_MAX) {
                int rg = r0g + rb + r;
                float zn = g_znorm[rg];
                for (int c = lane; c < NCODES; c += 32) {
                    float d = exact_d(z, cb, rg, c, zn, cn_s[c]);
                    unsigned long long key =
                        ((unsigned long long)__float_as_uint(d) << 32) | (unsigned)c;
                    atomicMin(&best_s[rb + r], key);
                }
            }
        }
    }
    __syncthreads();   // best_s final across all warps

    // ---- fused quantize tail: STE out, codes, loss partials ----
    {
        if (codes_out && tid < BM)
            codes_out[r0g + tid] = (float)(unsigned)(best_s[tid] & 0xFFFFFFFFu);

        float s = 0.0f;
        // 256 rows x 64 float4 = 16384 float4; 512 threads -> 32 each, coalesced
        #pragma unroll 4
        for (int it = 0; it < (BM * (DIM / 4)) / NTHREADS; it++) {
            const int idx = tid + it * NTHREADS;
            const int row = idx >> 6;
            const int col = idx & 63;
            const int code = (int)(unsigned)(best_s[row] & 0xFFFFFFFFu);
            float4 q4 = __ldg(reinterpret_cast<const float4*>(
                cb + (size_t)code * DIM) + col);
            float4 z4 = __ldg(reinterpret_cast<const float4*>(
                z + (size_t)(r0g + row) * DIM) + col);
            float4 o4;
            o4.x = __fadd_rn(z4.x, __fsub_rn(q4.x, z4.x));
            o4.y = __fadd_rn(z4.y, __fsub_rn(q4.y, z4.y));
            o4.z = __fadd_rn(z4.z, __fsub_rn(q4.z, z4.z));
            o4.w = __fadd_rn(z4.w, __fsub_rn(q4.w, z4.w));
            __stcs(reinterpret_cast<float4*>(out) +
                   ((size_t)(r0g + row) * (DIM / 4) + col), o4);
            float dx = q4.x - z4.x, dy = q4.y - z4.y;
            float dz = q4.z - z4.z, dw = q4.w - z4.w;
            s += dx * dx + dy * dy + dz * dz + dw * dw;
        }
        // block reduction (16 warps)
        #pragma unroll
        for (int off = 16; off > 0; off >>= 1)
            s += __shfl_down_sync(0xFFFFFFFFu, s, off);
        float* wsum = cn_s;      // reuse smem (cn no longer needed)
        __syncthreads();
        if (lane == 0) wsum[wid] = s;
        __syncthreads();
        if (tid == 0) {
            float bs = 0.0f;
            #pragma unroll
            for (int w = 0; w < 16; w++) bs += wsum[w];
            atomicAdd(&g_loss_acc, (double)bs);
            __threadfence();
            unsigned t = atomicAdd(&g_done, 1u);
            if (t == gridDim.x - 1) {        // last CTA finalizes
                g_done = 0u;
                if (loss_out)
                    *loss_out = (float)(1.25 * g_loss_acc /
                                        (double)((long long)N_ROWS * DIM));
            }
        }
    }
}

// -------------------------------------------------------------------------
extern "C" void kernel_launch(void* const* d_in, const int* in_sizes, int n_in,
                              void* d_out, int out_size) {
    const float* z  = (const float*)d_in[0];
    const float* cb = (const float*)d_in[1];
    float* out = (float*)d_out;

    static bool attr_done = false;
    if (!attr_done) {
        cudaFuncSetAttribute(screen_kernel,
                             cudaFuncAttributeMaxDynamicSharedMemorySize, SMEM_SZ);
        attr_done = true;
    }

    prep_kernel<<<NCODES / 256, 256>>>(cb);
    znorm_kernel<<<N_ROWS / ZROWS, 256>>>(z);

    const long long nd = (long long)N_ROWS * DIM;
    float* codes_out = (out_size >= (int)(nd + N_ROWS)) ? out + nd : nullptr;
    float* loss_out  = (out_size >= (int)(nd + N_ROWS + 1)) ? out + nd + N_ROWS
                                                            : nullptr;
    screen_kernel<<<N_ROWS / BM, NTHREADS, SMEM_SZ>>>(z, cb, out,
                                                      codes_out, loss_out);
}